// round 6
// baseline (speedup 1.0000x reference)
#include <cuda_runtime.h>
#include <math.h>

// input [256,1024] f32, W_xy [2304,1024] f32, b_xy [2304], w_out [5], b_out [1]
// out [256,256] f32
#define M_DIM 256
#define N_DIM 2304
#define K_DIM 1024
#define NN 256
#define COPIES 4

#define BM 64
#define BN 64
#define BK 16

// Scratch for xy = input @ W^T + b   (256*2304 floats = 2.36 MB)
__device__ float g_xy[M_DIM * N_DIM];

// ---------------- packed f32x2 helpers ----------------
__device__ __forceinline__ void fma2(unsigned long long& c,
                                     unsigned long long a,
                                     unsigned long long b) {
    asm("fma.rn.f32x2 %0, %1, %2, %0;" : "+l"(c) : "l"(a), "l"(b));
}
__device__ __forceinline__ float lo2(unsigned long long v) {
    return __int_as_float((int)(unsigned int)(v & 0xffffffffull));
}
__device__ __forceinline__ float hi2(unsigned long long v) {
    return __int_as_float((int)(unsigned int)(v >> 32));
}

// ---------------- Kernel 1: fp32 GEMM with pre-duplicated A tiles ----------
// xy[m,n] = sum_k A[m,k]*W[n,k] + b[n]
// Grid (36,4) = 144 blocks, 256 threads, 4x4 micro-tile via FFMA2.
// A tile stored in smem as float2{a,a} so FFMA2 needs no dup MOVs:
// per kk: 2 LDS.128 (a-dups) + 1 LDS.128 (b) + 8 FFMA2.
__global__ __launch_bounds__(256) void gemm_kernel(
    const float* __restrict__ A,     // [256,1024]
    const float* __restrict__ W,     // [2304,1024]
    const float* __restrict__ bias)  // [2304]
{
    __shared__ float2 As2[2][BK][BM + 2];   // dup pairs, row stride 66*8B
    __shared__ float  Ws4[2][BK][BN + 4];   // row stride 68*4B

    const int tid = threadIdx.x;
    const int row = tid >> 2;          // 0..63
    const int kk4 = (tid & 3) << 2;    // 0,4,8,12
    const int tx4 = (tid & 15) << 2;   // n offset 0..60
    const int ty4 = (tid >> 4) << 2;   // m offset 0..60
    const int m0  = blockIdx.y * BM;
    const int n0  = blockIdx.x * BN;

    const float* Aload = A + (size_t)(m0 + row) * K_DIM + kk4;
    const float* Wload = W + (size_t)(n0 + row) * K_DIM + kk4;

    unsigned long long acc[4][2];
#pragma unroll
    for (int r = 0; r < 4; ++r) { acc[r][0] = 0ull; acc[r][1] = 0ull; }

    // prologue: tile 0
    {
        float4 ra = *(const float4*)Aload;
        float4 rw = *(const float4*)Wload;
        As2[0][kk4 + 0][row] = make_float2(ra.x, ra.x);
        As2[0][kk4 + 1][row] = make_float2(ra.y, ra.y);
        As2[0][kk4 + 2][row] = make_float2(ra.z, ra.z);
        As2[0][kk4 + 3][row] = make_float2(ra.w, ra.w);
        Ws4[0][kk4 + 0][row] = rw.x; Ws4[0][kk4 + 1][row] = rw.y;
        Ws4[0][kk4 + 2][row] = rw.z; Ws4[0][kk4 + 3][row] = rw.w;
    }
    __syncthreads();

    const int KT = K_DIM / BK;  // 64
    for (int t = 0; t < KT; ++t) {
        const int cur = t & 1;
        float4 na, nw;
        if (t < KT - 1) {
            na = *(const float4*)(Aload + (t + 1) * BK);
            nw = *(const float4*)(Wload + (t + 1) * BK);
        }
#pragma unroll
        for (int kk = 0; kk < BK; ++kk) {
            const float2* ap = &As2[cur][kk][ty4];
            ulonglong2 a01 = *(const ulonglong2*)ap;
            ulonglong2 a23 = *(const ulonglong2*)(ap + 2);
            ulonglong2 b   = *(const ulonglong2*)&Ws4[cur][kk][tx4];
            fma2(acc[0][0], a01.x, b.x); fma2(acc[0][1], a01.x, b.y);
            fma2(acc[1][0], a01.y, b.x); fma2(acc[1][1], a01.y, b.y);
            fma2(acc[2][0], a23.x, b.x); fma2(acc[2][1], a23.x, b.y);
            fma2(acc[3][0], a23.y, b.x); fma2(acc[3][1], a23.y, b.y);
        }
        if (t < KT - 1) {
            const int nb = cur ^ 1;
            As2[nb][kk4 + 0][row] = make_float2(na.x, na.x);
            As2[nb][kk4 + 1][row] = make_float2(na.y, na.y);
            As2[nb][kk4 + 2][row] = make_float2(na.z, na.z);
            As2[nb][kk4 + 3][row] = make_float2(na.w, na.w);
            Ws4[nb][kk4 + 0][row] = nw.x; Ws4[nb][kk4 + 1][row] = nw.y;
            Ws4[nb][kk4 + 2][row] = nw.z; Ws4[nb][kk4 + 3][row] = nw.w;
        }
        __syncthreads();
    }

    const int gm = m0 + ty4;
    const int gn = n0 + tx4;
    float4 bb = *(const float4*)&bias[gn];
#pragma unroll
    for (int r = 0; r < 4; ++r) {
        float4 v;
        v.x = lo2(acc[r][0]) + bb.x;
        v.y = hi2(acc[r][0]) + bb.y;
        v.z = lo2(acc[r][1]) + bb.z;
        v.w = hi2(acc[r][1]) + bb.w;
        *(float4*)&g_xy[(size_t)(gm + r) * N_DIM + gn] = v;
    }
}

// ---------------- Kernel 2: register-tiled soft-XOR + 1x1 conv -------------
// One block per batch element, 256 threads.
// Thread t: jg = t&63 owns j = 4*jg..4*jg+3;  iset = t>>6 handles igs
// ig = iset, iset+4, ... (16 i-groups). For each i-group the 4x4 (i,j) tile
// needs only ey-group ig^jg: 8 LDS.128 feed 32 FFMA2 (2 B/FMA).
// ey is XOR-swizzled (q ^= (q>>3)&7 at float4 granularity) so the 64B-strided
// group loads are conflict-free (4 phases per LDS.128, bandwidth-optimal).
__global__ __launch_bounds__(256) void softxor_kernel(
    const float* __restrict__ w_out,  // [5]
    const float* __restrict__ b_out,  // [1]
    float* __restrict__ out)          // [256,256]
{
    __shared__ float4 ex[NN];               // 4KB
    __shared__ float4 ey[NN];               // 4KB, swizzled
    __shared__ float4 part[3][64][4];       // 12KB partial sums

    const int b = blockIdx.x;
    const int t = threadIdx.x;
    const float* row = g_xy + (size_t)b * N_DIM;

    {
        float4 e, f;
        e.x = expf(row[0 * NN + t]);
        e.y = expf(row[1 * NN + t]);
        e.z = expf(row[2 * NN + t]);
        e.w = expf(row[3 * NN + t]);
        f.x = expf(row[4 * NN + t]);
        f.y = expf(row[5 * NN + t]);
        f.z = expf(row[6 * NN + t]);
        f.w = expf(row[7 * NN + t]);
        ex[t] = e;
        ey[t ^ ((t >> 3) & 7)] = f;  // store at swizzled position
    }
    __syncthreads();

    const int jg   = t & 63;
    const int iset = t >> 6;

    ulonglong2 a0 = {0ull, 0ull}, a1 = {0ull, 0ull};
    ulonglong2 a2 = {0ull, 0ull}, a3 = {0ull, 0ull};

    for (int ig = iset; ig < 64; ig += 4) {
        const int g  = ig ^ jg;
        const int h  = (g >> 1) & 7;
        const int yb = (4 * g) ^ (h & 4);   // swizzled base of ey group g
        const int h3 = h & 3;

        ulonglong2 x0 = *(const ulonglong2*)(ex + 4 * ig + 0);
        ulonglong2 x1 = *(const ulonglong2*)(ex + 4 * ig + 1);
        ulonglong2 x2 = *(const ulonglong2*)(ex + 4 * ig + 2);
        ulonglong2 x3 = *(const ulonglong2*)(ex + 4 * ig + 3);
        // y_k = logical ey[4g+k], fetched from swizzled slot yb + (k^h3)
        ulonglong2 y0 = *(const ulonglong2*)(ey + yb + (0 ^ h3));
        ulonglong2 y1 = *(const ulonglong2*)(ey + yb + (1 ^ h3));
        ulonglong2 y2 = *(const ulonglong2*)(ey + yb + (2 ^ h3));
        ulonglong2 y3 = *(const ulonglong2*)(ey + yb + (3 ^ h3));

        // acc[jl] += sum_il x_il * y_(il^jl)
        fma2(a0.x, x0.x, y0.x); fma2(a0.y, x0.y, y0.y);
        fma2(a0.x, x1.x, y1.x); fma2(a0.y, x1.y, y1.y);
        fma2(a0.x, x2.x, y2.x); fma2(a0.y, x2.y, y2.y);
        fma2(a0.x, x3.x, y3.x); fma2(a0.y, x3.y, y3.y);

        fma2(a1.x, x0.x, y1.x); fma2(a1.y, x0.y, y1.y);
        fma2(a1.x, x1.x, y0.x); fma2(a1.y, x1.y, y0.y);
        fma2(a1.x, x2.x, y3.x); fma2(a1.y, x2.y, y3.y);
        fma2(a1.x, x3.x, y2.x); fma2(a1.y, x3.y, y2.y);

        fma2(a2.x, x0.x, y2.x); fma2(a2.y, x0.y, y2.y);
        fma2(a2.x, x1.x, y3.x); fma2(a2.y, x1.y, y3.y);
        fma2(a2.x, x2.x, y0.x); fma2(a2.y, x2.y, y0.y);
        fma2(a2.x, x3.x, y1.x); fma2(a2.y, x3.y, y1.y);

        fma2(a3.x, x0.x, y3.x); fma2(a3.y, x0.y, y3.y);
        fma2(a3.x, x1.x, y2.x); fma2(a3.y, x1.y, y2.y);
        fma2(a3.x, x2.x, y1.x); fma2(a3.y, x2.y, y1.y);
        fma2(a3.x, x3.x, y0.x); fma2(a3.y, x3.y, y0.y);
    }

    // reduce the 4 i-sets
    if (iset > 0) {
        part[iset - 1][jg][0] = *(const float4*)&a0;
        part[iset - 1][jg][1] = *(const float4*)&a1;
        part[iset - 1][jg][2] = *(const float4*)&a2;
        part[iset - 1][jg][3] = *(const float4*)&a3;
    }
    __syncthreads();

    if (iset == 0) {
        float4 s[4];
        s[0] = *(const float4*)&a0;
        s[1] = *(const float4*)&a1;
        s[2] = *(const float4*)&a2;
        s[3] = *(const float4*)&a3;
#pragma unroll
        for (int ss = 0; ss < 3; ++ss) {
#pragma unroll
            for (int jl = 0; jl < 4; ++jl) {
                float4 p = part[ss][jg][jl];
                s[jl].x += p.x; s[jl].y += p.y; s[jl].z += p.z; s[jl].w += p.w;
            }
        }
        const float w0 = w_out[0], w1 = w_out[1], w2 = w_out[2],
                    w3 = w_out[3], w4 = w_out[4], bo = b_out[0];
        float4 sk = *(const float4*)(row + 8 * NN + 4 * jg);
        const float* skp = (const float*)&sk;
        float4 o;
        float* op = (float*)&o;
#pragma unroll
        for (int jl = 0; jl < 4; ++jl) {
            op[jl] = w0 * logf(s[jl].x) + w1 * logf(s[jl].y)
                   + w2 * logf(s[jl].z) + w3 * logf(s[jl].w)
                   + w4 * skp[jl] + bo;
        }
        *(float4*)(out + (size_t)b * NN + 4 * jg) = o;
    }
}

// ---------------- launch ----------------
extern "C" void kernel_launch(void* const* d_in, const int* in_sizes, int n_in,
                              void* d_out, int out_size) {
    const float* inp  = (const float*)d_in[0];
    const float* W    = (const float*)d_in[1];
    const float* bxy  = (const float*)d_in[2];
    const float* wout = (const float*)d_in[3];
    const float* bout = (const float*)d_in[4];
    float* out = (float*)d_out;

    dim3 grid(N_DIM / BN, M_DIM / BM);  // (36, 4)
    gemm_kernel<<<grid, 256>>>(inp, W, bxy);
    softxor_kernel<<<M_DIM, NN>>>(wout, bout, out);
}